// round 15
// baseline (speedup 1.0000x reference)
#include <cuda_runtime.h>
#include <cuda_bf16.h>
#include <math.h>
#include <stdint.h>

#define BATCH  2
#define SEQ    2048
#define DMODEL 1024
#define NHEADS 16
#define DK     64
#define WIN    256
#define NTOK   (BATCH * SEQ)
#define TSZ    (NTOK * DMODEL)

// -------- scratch (allocation-free rule: __device__ globals) --------
__device__ __nv_bfloat16 g_pr_hi[3 * TSZ];   // projected Q,K,V split
__device__ __nv_bfloat16 g_pr_lo[3 * TSZ];
__device__ float         g_ctx[TSZ];         // attention ctx (fp32)
__device__ __nv_bfloat16 g_wt_hi[4 * DMODEL * DMODEL];  // W^T split
__device__ __nv_bfloat16 g_wt_lo[4 * DMODEL * DMODEL];

// -------- helpers --------
__device__ __forceinline__ uint32_t s2u(const void* p) {
    uint32_t a;
    asm("{ .reg .u64 t; cvta.to.shared.u64 t, %1; cvt.u32.u64 %0, t; }"
        : "=r"(a) : "l"(p));
    return a;
}
__device__ __forceinline__ void ldmx4(uint32_t* r, uint32_t addr) {
    asm volatile("ldmatrix.sync.aligned.m8n8.x4.shared.b16 {%0,%1,%2,%3}, [%4];"
                 : "=r"(r[0]), "=r"(r[1]), "=r"(r[2]), "=r"(r[3]) : "r"(addr));
}
__device__ __forceinline__ void ldmx4t(uint32_t* r, uint32_t addr) {
    asm volatile("ldmatrix.sync.aligned.m8n8.x4.trans.shared.b16 {%0,%1,%2,%3}, [%4];"
                 : "=r"(r[0]), "=r"(r[1]), "=r"(r[2]), "=r"(r[3]) : "r"(addr));
}
__device__ __forceinline__ void mma_bf16(float* c, const uint32_t* a, const uint32_t* b) {
    asm volatile(
        "mma.sync.aligned.m16n8k16.row.col.f32.bf16.bf16.f32 "
        "{%0,%1,%2,%3}, {%4,%5,%6,%7}, {%8,%9}, {%0,%1,%2,%3};"
        : "+f"(c[0]), "+f"(c[1]), "+f"(c[2]), "+f"(c[3])
        : "r"(a[0]), "r"(a[1]), "r"(a[2]), "r"(a[3]), "r"(b[0]), "r"(b[1]));
}
#define CP_ASYNC16(dst, src) \
    asm volatile("cp.async.ca.shared.global [%0], [%1], 16;" :: "r"(dst), "l"(src))
#define CP_ASYNC16_Z(dst, src, sz) \
    asm volatile("cp.async.ca.shared.global [%0], [%1], 16, %2;" :: "r"(dst), "l"(src), "r"(sz))
#define CP_COMMIT()  asm volatile("cp.async.commit_group;" ::: "memory")
#define CP_WAIT0()   asm volatile("cp.async.wait_group 0;" ::: "memory")
#define CP_WAIT1()   asm volatile("cp.async.wait_group 1;" ::: "memory")

__device__ __forceinline__ uint32_t hi_pack(float a, float b) {
    return __byte_perm(__float_as_uint(a), __float_as_uint(b), 0x7632);
}
__device__ __forceinline__ uint32_t lo_pack(float a, float b) {
    float ra = a - __uint_as_float(__float_as_uint(a) & 0xffff0000u);
    float rb = b - __uint_as_float(__float_as_uint(b) & 0xffff0000u);
    __nv_bfloat162 p = __floats2bfloat162_rn(ra, rb);
    return *(uint32_t*)&p;
}

// ==================== weight prep: Wt[n,k] = W[k,n], split hi/lo ====================
struct WPrep { const float* w[4]; };

__global__ __launch_bounds__(256)
void prep_w(WPrep wp, __nv_bfloat16* __restrict__ hi, __nv_bfloat16* __restrict__ lo) {
    __shared__ float t[32][33];
    const int wi = blockIdx.z;
    const float* W = wp.w[wi];
    const int n0 = blockIdx.x * 32, k0 = blockIdx.y * 32;
    const int tx = threadIdx.x & 31, ty = (threadIdx.x >> 5) * 4;
    #pragma unroll
    for (int i = 0; i < 4; i++)
        t[ty + i][tx] = W[(size_t)(k0 + ty + i) * DMODEL + n0 + tx];
    __syncthreads();
    #pragma unroll
    for (int i = 0; i < 4; i++) {
        float a = t[tx][ty + i];
        __nv_bfloat16 h = __float2bfloat16_rz(a);
        float hf = __bfloat162float(h);
        __nv_bfloat16 l = __float2bfloat16(a - hf);
        size_t idx = (size_t)wi * DMODEL * DMODEL + (size_t)(n0 + ty + i) * DMODEL + k0 + tx;
        hi[idx] = h;
        lo[idx] = l;
    }
}

// ==================== HMMA split-bf16 GEMM ====================
// CTA tile 128(M) x 256(N), K chunk 32, 3-stage ring (48KB/stage).
// 8 warps as 2(M) x 4(N); warp tile 64x64.
#define GSTG 49152

struct GemmJob {
    const float* A[3];
    const __nv_bfloat16* Bh[3];
    const __nv_bfloat16* Bl[3];
    const float* bias[3];
    __nv_bfloat16 *Ch[3], *Cl[3];
};

template <bool BF16OUT>
__device__ __forceinline__
void gemm_mma_body(const float* __restrict__ A, const __nv_bfloat16* __restrict__ Bh,
                   const __nv_bfloat16* __restrict__ Bl, const float* __restrict__ bias,
                   float* __restrict__ C, __nv_bfloat16* __restrict__ Ch,
                   __nv_bfloat16* __restrict__ Cl) {
    extern __shared__ char smx[];
    const int tid = threadIdx.x, lane = tid & 31, wid = tid >> 5;
    const int brow = blockIdx.y << 7, bcol = blockIdx.x << 8;
    const int wm = (wid >> 2) << 6;       // 0, 64
    const int wn = (wid & 3) << 6;        // 0, 64, 128, 192

    const uint32_t sbase = s2u(smx);

    float acc[4][8][4];
    #pragma unroll
    for (int i = 0; i < 4; i++)
        #pragma unroll
        for (int j = 0; j < 8; j++)
            #pragma unroll
            for (int u = 0; u < 4; u++) acc[i][j][u] = 0.f;

    auto loadB = [&](int stg, int k0) {
        const uint32_t d0 = sbase + (uint32_t)stg * GSTG + 16384u;
        #pragma unroll
        for (int it = 0; it < 8; it++) {
            int f = tid + it * 256;
            int row = f >> 3, g = f & 7;
            const __nv_bfloat16* src = (g < 4 ? Bh : Bl) + (size_t)(bcol + row) * DMODEL + k0 + (g & 3) * 8;
            CP_ASYNC16(d0 + row * 128 + ((g ^ (row & 7)) << 4), src);
        }
        CP_COMMIT();
    };
    auto loadA = [&](int stg, int k0) {
        char* dst = smx + (size_t)stg * GSTG;
        #pragma unroll
        for (int it = 0; it < 2; it++) {
            int f = tid + it * 256;
            int row = f >> 2, grp = f & 3;
            const float* ap = A + (size_t)(brow + row) * DMODEL + k0 + grp * 8;
            float4 f0 = *(const float4*)ap, f1 = *(const float4*)(ap + 4);
            uint4 ah = make_uint4(hi_pack(f0.x, f0.y), hi_pack(f0.z, f0.w),
                                  hi_pack(f1.x, f1.y), hi_pack(f1.z, f1.w));
            uint4 al = make_uint4(lo_pack(f0.x, f0.y), lo_pack(f0.z, f0.w),
                                  lo_pack(f1.x, f1.y), lo_pack(f1.z, f1.w));
            *(uint4*)(dst + row * 128 + ((grp ^ (row & 7)) << 4)) = ah;
            *(uint4*)(dst + row * 128 + (((grp + 4) ^ (row & 7)) << 4)) = al;
        }
    };

    // ---- prologue: stages 0, 1 ----
    loadB(0, 0);  loadA(0, 0);
    loadB(1, 32); loadA(1, 32);

    for (int kt = 0; kt < 32; kt++) {
        // wait for stage kt's B (its group was committed >=2 iterations ago)
        if (kt < 31) { CP_WAIT1(); } else { CP_WAIT0(); }
        __syncthreads();

        // issue loads for stage kt+2 (ring slot (kt+2)%3 == (kt-1)%3, now free)
        if (kt < 30) {
            loadB((kt + 2) % 3, (kt + 2) << 5);
            loadA((kt + 2) % 3, (kt + 2) << 5);
        }

        const uint32_t aBase = sbase + (uint32_t)(kt % 3) * GSTG;
        const uint32_t bBase = aBase + 16384u;
        #pragma unroll
        for (int ks2 = 0; ks2 < 2; ks2++) {
            uint32_t aH[4][4], aL[4][4];
            const int cA = (ks2 << 1) + (lane >> 4);
            #pragma unroll
            for (int i = 0; i < 4; i++) {
                int r = wm + i * 16 + (lane & 15);
                ldmx4(aH[i], aBase + r * 128 + ((cA ^ (r & 7)) << 4));
                ldmx4(aL[i], aBase + r * 128 + (((cA + 4) ^ (r & 7)) << 4));
            }
            const int cB = (ks2 << 1) + ((lane >> 3) & 1);
            #pragma unroll
            for (int jp = 0; jp < 4; jp++) {
                int rn = wn + jp * 16 + (lane & 7) + ((lane >> 4) & 1) * 8;
                uint32_t bh4[4], bl4[4];
                ldmx4(bh4, bBase + rn * 128 + ((cB ^ (rn & 7)) << 4));
                ldmx4(bl4, bBase + rn * 128 + (((cB + 4) ^ (rn & 7)) << 4));
                #pragma unroll
                for (int i = 0; i < 4; i++) {
                    mma_bf16(acc[i][jp * 2], aH[i], bh4);
                    mma_bf16(acc[i][jp * 2], aH[i], bl4);
                    mma_bf16(acc[i][jp * 2], aL[i], bh4);
                    mma_bf16(acc[i][jp * 2 + 1], aH[i], bh4 + 2);
                    mma_bf16(acc[i][jp * 2 + 1], aH[i], bl4 + 2);
                    mma_bf16(acc[i][jp * 2 + 1], aL[i], bh4 + 2);
                }
            }
        }
    }
    __syncthreads();

    const int g = lane >> 2, tg = lane & 3;
    #pragma unroll
    for (int i = 0; i < 4; i++) {
        const int r0 = brow + wm + i * 16 + g;
        #pragma unroll
        for (int j = 0; j < 8; j++) {
            const int col = bcol + wn + j * 8 + tg * 2;
            float2 bb = *(const float2*)(bias + col);
            float v0 = acc[i][j][0] + bb.x, v1 = acc[i][j][1] + bb.y;
            float v2 = acc[i][j][2] + bb.x, v3 = acc[i][j][3] + bb.y;
            if (BF16OUT) {
                *(uint32_t*)(Ch + (size_t)r0 * DMODEL + col)       = hi_pack(v0, v1);
                *(uint32_t*)(Cl + (size_t)r0 * DMODEL + col)       = lo_pack(v0, v1);
                *(uint32_t*)(Ch + (size_t)(r0 + 8) * DMODEL + col) = hi_pack(v2, v3);
                *(uint32_t*)(Cl + (size_t)(r0 + 8) * DMODEL + col) = lo_pack(v2, v3);
            } else {
                *(float2*)(C + (size_t)r0 * DMODEL + col)       = make_float2(v0, v1);
                *(float2*)(C + (size_t)(r0 + 8) * DMODEL + col) = make_float2(v2, v3);
            }
        }
    }
}

__global__ __launch_bounds__(256, 1)
void gemm_mma_qkv(GemmJob job) {
    const int z = blockIdx.z;
    gemm_mma_body<true>(job.A[z], job.Bh[z], job.Bl[z], job.bias[z],
                        nullptr, job.Ch[z], job.Cl[z]);
}

__global__ __launch_bounds__(256, 1)
void gemm_mma_one(const float* __restrict__ A, const __nv_bfloat16* __restrict__ Bh,
                  const __nv_bfloat16* __restrict__ Bl, const float* __restrict__ bias,
                  float* __restrict__ C) {
    gemm_mma_body<false>(A, Bh, Bl, bias, C, nullptr, nullptr);
}

// ==================== HMMA sliding-window attention (R11 verbatim) ====================
#define SQH 0
#define SQL 8192
#define SKH 16384
#define SKL 32768
#define SVH 49152
#define SVL 65536
#define SMP 81920
#define SLP 82432
#define ATTN_SMEM_B 83968

__device__ __forceinline__
void attn_cp128(const __nv_bfloat16* __restrict__ Hsrc, const __nv_bfloat16* __restrict__ Lsrc,
                uint32_t dhi, uint32_t dlo, int kbase, int hi_local, int tid) {
    #pragma unroll
    for (int it = 0; it < 8; it++) {
        int f = tid + it * 256;
        int buf = f >> 10;
        int rr = (f >> 3) & 127;
        int gr = f & 7;
        int kr = kbase + rr;
        uint32_t sz = (kr <= hi_local) ? 16u : 0u;
        int srow = (kr <= hi_local) ? kr : hi_local;
        const __nv_bfloat16* s = (buf ? Lsrc : Hsrc) + (size_t)srow * DMODEL + gr * 8;
        uint32_t d = (buf ? dlo : dhi) + rr * 128 + ((gr ^ (rr & 7)) << 4);
        CP_ASYNC16_Z(d, s, sz);
    }
}

__device__ __forceinline__
void qk_mma(float acc[8][4], uint32_t qh, uint32_t ql, uint32_t kh, uint32_t kl,
            int wm, int wnh, int lane) {
    #pragma unroll
    for (int j = 0; j < 8; j++)
        #pragma unroll
        for (int u = 0; u < 4; u++) acc[j][u] = 0.f;
    #pragma unroll
    for (int ks = 0; ks < 4; ks++) {
        uint32_t aH[4], aL[4];
        int ar = wm + (lane & 15);
        int cA = ks * 2 + (lane >> 4);
        uint32_t aoff = ar * 128 + ((cA ^ (ar & 7)) << 4);
        ldmx4(aH, qh + aoff);
        ldmx4(aL, ql + aoff);
        int cB = ks * 2 + ((lane >> 3) & 1);
        #pragma unroll
        for (int jp = 0; jp < 4; jp++) {
            int rn = wnh * 64 + jp * 16 + (lane & 7) + ((lane >> 4) & 1) * 8;
            uint32_t boff = rn * 128 + ((cB ^ (rn & 7)) << 4);
            uint32_t bh4[4], bl4[4];
            ldmx4(bh4, kh + boff);
            ldmx4(bl4, kl + boff);
            mma_bf16(acc[jp * 2], aH, bh4);
            mma_bf16(acc[jp * 2], aH, bl4);
            mma_bf16(acc[jp * 2], aL, bh4);
            mma_bf16(acc[jp * 2 + 1], aH, bh4 + 2);
            mma_bf16(acc[jp * 2 + 1], aH, bl4 + 2);
            mma_bf16(acc[jp * 2 + 1], aL, bh4 + 2);
        }
    }
}

__global__ __launch_bounds__(256, 2)
void attn_mma(float* __restrict__ attnp) {
    extern __shared__ char sax[];
    float* sMp = (float*)(sax + SMP);
    float* sLp = (float*)(sax + SLP);

    const int qt = blockIdx.x, h = blockIdx.y, b = blockIdx.z;
    const int q0 = qt * 64;
    const int tid = threadIdx.x, lane = tid & 31, w = tid >> 5;
    const int wm = (w >> 1) << 4;
    const int wnh = w & 1;
    const int g = lane >> 2, tg = lane & 3;

    const int lo  = max(0, q0 - WIN);
    const int hi  = min(SEQ - 1, q0 + 63 + WIN);
    const int cnt = hi - lo + 1;
    const int nch = (cnt + 127) >> 7;

    const uint32_t qh = s2u(sax) + SQH, ql = s2u(sax) + SQL;
    const uint32_t kh = s2u(sax) + SKH, kl = s2u(sax) + SKL;
    const uint32_t vh = s2u(sax) + SVH, vl = s2u(sax) + SVL;

    const size_t hoff = (size_t)(b * SEQ) * DMODEL + h * DK;
    const __nv_bfloat16* Qh = g_pr_hi + hoff;
    const __nv_bfloat16* Ql = g_pr_lo + hoff;
    const __nv_bfloat16* Kh = g_pr_hi + TSZ + hoff;
    const __nv_bfloat16* Kl = g_pr_lo + TSZ + hoff;
    const __nv_bfloat16* Vh = g_pr_hi + 2 * (size_t)TSZ + hoff;
    const __nv_bfloat16* Vl = g_pr_lo + 2 * (size_t)TSZ + hoff;

    // ---- Q tile via cp.async ----
    #pragma unroll
    for (int it = 0; it < 4; it++) {
        int f = tid + it * 256;
        int buf = f >> 9;
        int rr = (f >> 3) & 63;
        int gr = f & 7;
        const __nv_bfloat16* s = (buf ? Ql : Qh) + (size_t)(q0 + rr) * DMODEL + gr * 8;
        uint32_t d = (buf ? ql : qh) + rr * 128 + ((gr ^ (rr & 7)) << 4);
        CP_ASYNC16(d, s);
    }
    CP_COMMIT();

    const int qg0 = q0 + wm + g, qg1 = qg0 + 8;
    const int jlo0 = max(lo, qg0 - WIN), jhi0 = min(hi, qg0 + WIN);
    const int jlo1 = max(lo, qg1 - WIN), jhi1 = min(hi, qg1 + WIN);

    // ---- pass 1: online (m, l), K double-buffered across (kh,kl)/(vh,vl) ----
    attn_cp128(Kh, Kl, kh, kl, lo, hi, tid);
    CP_COMMIT();

    float m0 = -1e30f, m1 = -1e30f, l0 = 0.f, l1 = 0.f;
    for (int c = 0; c < nch; c++) {
        if (c + 1 < nch) {
            uint32_t dh = ((c + 1) & 1) ? vh : kh;
            uint32_t dl = ((c + 1) & 1) ? vl : kl;
            attn_cp128(Kh, Kl, dh, dl, lo + (c + 1) * 128, hi, tid);
            CP_COMMIT();
            CP_WAIT1();
        } else {
            CP_WAIT0();
        }
        __syncthreads();

        uint32_t ch_ = (c & 1) ? vh : kh;
        uint32_t cl_ = (c & 1) ? vl : kl;
        float acc[8][4];
        qk_mma(acc, qh, ql, ch_, cl_, wm, wnh, lane);

        const int cb = lo + c * 128 + wnh * 64;
        float cmax0 = -1e30f, cmax1 = -1e30f;
        #pragma unroll
        for (int j = 0; j < 8; j++) {
            int jg = cb + j * 8 + tg * 2;
            #pragma unroll
            for (int u = 0; u < 4; u++) acc[j][u] *= 0.125f;
            if (jg     >= jlo0 && jg     <= jhi0) cmax0 = fmaxf(cmax0, acc[j][0]);
            if (jg + 1 >= jlo0 && jg + 1 <= jhi0) cmax0 = fmaxf(cmax0, acc[j][1]);
            if (jg     >= jlo1 && jg     <= jhi1) cmax1 = fmaxf(cmax1, acc[j][2]);
            if (jg + 1 >= jlo1 && jg + 1 <= jhi1) cmax1 = fmaxf(cmax1, acc[j][3]);
        }
        cmax0 = fmaxf(cmax0, __shfl_xor_sync(0xffffffffu, cmax0, 1));
        cmax0 = fmaxf(cmax0, __shfl_xor_sync(0xffffffffu, cmax0, 2));
        cmax1 = fmaxf(cmax1, __shfl_xor_sync(0xffffffffu, cmax1, 1));
        cmax1 = fmaxf(cmax1, __shfl_xor_sync(0xffffffffu, cmax1, 2));

        float mn0 = fmaxf(m0, cmax0), mn1 = fmaxf(m1, cmax1);
        float s0 = 0.f, s1 = 0.f;
        #pragma unroll
        for (int j = 0; j < 8; j++) {
            int jg = cb + j * 8 + tg * 2;
            if (jg     >= jlo0 && jg     <= jhi0) s0 += __expf(acc[j][0] - mn0);
            if (jg + 1 >= jlo0 && jg + 1 <= jhi0) s0 += __expf(acc[j][1] - mn0);
            if (jg     >= jlo1 && jg     <= jhi1) s1 += __expf(acc[j][2] - mn1);
            if (jg + 1 >= jlo1 && jg + 1 <= jhi1) s1 += __expf(acc[j][3] - mn1);
        }
        s0 += __shfl_xor_sync(0xffffffffu, s0, 1);
        s0 += __shfl_xor_sync(0xffffffffu, s0, 2);
        s1 += __shfl_xor_sync(0xffffffffu, s1, 1);
        s1 += __shfl_xor_sync(0xffffffffu, s1, 2);

        l0 = (m0 > -1e29f ? l0 * __expf(m0 - mn0) : 0.f) + s0;
        l1 = (m1 > -1e29f ? l1 * __expf(m1 - mn1) : 0.f) + s1;
        m0 = mn0; m1 = mn1;
        __syncthreads();
    }

    // ---- merge halves; prefetch pass-2 chunk 0 under the merge ----
    if (tg == 0) {
        sMp[wnh * 64 + wm + g]     = m0;  sLp[wnh * 64 + wm + g]     = l0;
        sMp[wnh * 64 + wm + g + 8] = m1;  sLp[wnh * 64 + wm + g + 8] = l1;
    }
    attn_cp128(Kh, Kl, kh, kl, lo, hi, tid);
    attn_cp128(Vh, Vl, vh, vl, lo, hi, tid);
    CP_COMMIT();
    __syncthreads();

    float mf0, mf1, li0, li1;
    {
        int r0 = wm + g, r1 = r0 + 8;
        float ma = sMp[r0], mb2 = sMp[64 + r0];
        float la = sLp[r0], lb2 = sLp[64 + r0];
        mf0 = fmaxf(ma, mb2);
        li0 = 1.f / (la * __expf(ma - mf0) + lb2 * __expf(mb2 - mf0));
        ma = sMp[r1]; mb2 = sMp[64 + r1];
        la = sLp[r1]; lb2 = sLp[64 + r1];
        mf1 = fmaxf(ma, mb2);
        li1 = 1.f / (la * __expf(ma - mf1) + lb2 * __expf(mb2 - mf1));
    }

    float* baseA = nullptr;
    if (attnp) {
        baseA = attnp + ((size_t)((b * NHEADS + h) * SEQ + q0)) * SEQ;
        const int z2 = min((int)SEQ, lo + nch * 128);
        for (int f = tid; f < 64 * 512; f += 256) {
            int m = f >> 9, c4 = (f & 511) << 2;
            if (c4 < lo || c4 >= z2)
                *(float4*)(baseA + (size_t)m * SEQ + c4) = make_float4(0.f, 0.f, 0.f, 0.f);
        }
    }

    // ---- pass 2 ----
    float oacc[4][4];
    #pragma unroll
    for (int j = 0; j < 4; j++)
        #pragma unroll
        for (int u = 0; u < 4; u++) oacc[j][u] = 0.f;

    for (int c = 0; c < nch; c++) {
        CP_WAIT0();
        __syncthreads();
        float acc[8][4];
        qk_mma(acc, qh, ql, kh, kl, wm, wnh, lane);

        const int cb = lo + c * 128 + wnh * 64;
        #pragma unroll
        for (int j = 0; j < 8; j++) {
            int jg = cb + j * 8 + tg * 2;
            float p0 = (jg     >= jlo0 && jg     <= jhi0) ? __expf(acc[j][0] * 0.125f - mf0) * li0 : 0.f;
            float p1 = (jg + 1 >= jlo0 && jg + 1 <= jhi0) ? __expf(acc[j][1] * 0.125f - mf0) * li0 : 0.f;
            float p2 = (jg     >= jlo1 && jg     <= jhi1) ? __expf(acc[j][2] * 0.125f - mf1) * li1 : 0.f;
            float p3 = (jg + 1 >= jlo1 && jg + 1 <= jhi1) ? __expf(acc[j][3] * 0.125f - mf1) * li1 : 0.f;
            acc[j][0] = p0; acc[j][1] = p1; acc[j][2] = p2; acc[j][3] = p3;
            if (baseA && jg < SEQ) {
                *(float2*)(baseA + (size_t)(wm + g) * SEQ + jg)     = make_float2(p0, p1);
                *(float2*)(baseA + (size_t)(wm + g + 8) * SEQ + jg) = make_float2(p2, p3);
            }
        }
        __syncthreads();

        #pragma unroll
        for (int j = 0; j < 8; j++) {
            int col = wnh * 64 + j * 8 + tg * 2;
            int sub = col >> 6, c64 = col & 63;
            int r0 = wm + g, r1 = r0 + 8;
            int o0 = sub * 8192 + r0 * 128 + ((((c64 >> 3)) ^ (r0 & 7)) << 4) + (c64 & 7) * 2;
            int o1 = sub * 8192 + r1 * 128 + ((((c64 >> 3)) ^ (r1 & 7)) << 4) + (c64 & 7) * 2;
            *(uint32_t*)(sax + SKH + o0) = hi_pack(acc[j][0], acc[j][1]);
            *(uint32_t*)(sax + SKL + o0) = lo_pack(acc[j][0], acc[j][1]);
            *(uint32_t*)(sax + SKH + o1) = hi_pack(acc[j][2], acc[j][3]);
            *(uint32_t*)(sax + SKL + o1) = lo_pack(acc[j][2], acc[j][3]);
        }
        __syncthreads();

        #pragma unroll
        for (int ks = 0; ks < 8; ks++) {
            uint32_t aH[4], aL[4];
            int ar = wm + (lane & 15);
            int sub = ks >> 2;
            int cA = (ks & 3) * 2 + (lane >> 4);
            uint32_t aoff = sub * 8192 + ar * 128 + ((cA ^ (ar & 7)) << 4);
            ldmx4(aH, kh + aoff);
            ldmx4(aL, kl + aoff);
            #pragma unroll
            for (int jp = 0; jp < 2; jp++) {
                int rv = ks * 16 + (lane & 15);
                int gd = wnh * 4 + jp * 2 + (lane >> 4);
                uint32_t boff = rv * 128 + ((gd ^ (rv & 7)) << 4);
                uint32_t vh4[4], vl4[4];
                ldmx4t(vh4, vh + boff);
                ldmx4t(vl4, vl + boff);
                mma_bf16(oacc[jp * 2], aH, vh4);
                mma_bf16(oacc[jp * 2], aH, vl4);
                mma_bf16(oacc[jp * 2], aL, vh4);
                mma_bf16(oacc[jp * 2 + 1], aH, vh4 + 2);
                mma_bf16(oacc[jp * 2 + 1], aH, vl4 + 2);
                mma_bf16(oacc[jp * 2 + 1], aL, vh4 + 2);
            }
        }

        if (c + 1 < nch) {
            __syncthreads();
            attn_cp128(Kh, Kl, kh, kl, lo + (c + 1) * 128, hi, tid);
            attn_cp128(Vh, Vl, vh, vl, lo + (c + 1) * 128, hi, tid);
            CP_COMMIT();
        }
    }

    // ---- write ctx (fp32, feeds O-proj) ----
    {
        float* cb2 = g_ctx + ((size_t)(b * SEQ + q0 + wm + g)) * DMODEL + h * DK + wnh * 32;
        #pragma unroll
        for (int j = 0; j < 4; j++) {
            int col = j * 8 + tg * 2;
            *(float2*)(cb2 + col)              = make_float2(oacc[j][0], oacc[j][1]);
            *(float2*)(cb2 + 8 * DMODEL + col) = make_float2(oacc[j][2], oacc[j][3]);
        }
    }
}

// ==================== launch ====================
extern "C" void kernel_launch(void* const* d_in, const int* in_sizes, int n_in,
                              void* d_out, int out_size) {
    const float* q  = (const float*)d_in[0];
    const float* k  = (const float*)d_in[1];
    const float* v  = (const float*)d_in[2];
    const float* Wq = (const float*)d_in[3];
    const float* bq = (const float*)d_in[4];
    const float* Wk = (const float*)d_in[5];
    const float* bk = (const float*)d_in[6];
    const float* Wv = (const float*)d_in[7];
    const float* bv = (const float*)d_in[8];
    const float* Wo = (const float*)d_in[9];
    const float* bo = (const float*)d_in[10];

    __nv_bfloat16 *prh, *prl, *wth, *wtl;
    float* ctx;
    cudaGetSymbolAddress((void**)&prh, g_pr_hi);
    cudaGetSymbolAddress((void**)&prl, g_pr_lo);
    cudaGetSymbolAddress((void**)&ctx, g_ctx);
    cudaGetSymbolAddress((void**)&wth, g_wt_hi);
    cudaGetSymbolAddress((void**)&wtl, g_wt_lo);

    const int GEMM_SMEM = 3 * GSTG;   // 147456
    cudaFuncSetAttribute(gemm_mma_qkv, cudaFuncAttributeMaxDynamicSharedMemorySize, GEMM_SMEM);
    cudaFuncSetAttribute(gemm_mma_one, cudaFuncAttributeMaxDynamicSharedMemorySize, GEMM_SMEM);
    cudaFuncSetAttribute(attn_mma, cudaFuncAttributeMaxDynamicSharedMemorySize, ATTN_SMEM_B);

    WPrep wp;
    wp.w[0] = Wq; wp.w[1] = Wk; wp.w[2] = Wv; wp.w[3] = Wo;
    dim3 pgrid(DMODEL / 32, DMODEL / 32, 4);
    prep_w<<<pgrid, 256>>>(wp, wth, wtl);

    GemmJob job;
    const size_t WSZ = (size_t)DMODEL * DMODEL;
    job.A[0] = q;  job.A[1] = k;  job.A[2] = v;
    for (int z = 0; z < 3; z++) {
        job.Bh[z] = wth + (size_t)z * WSZ;
        job.Bl[z] = wtl + (size_t)z * WSZ;
        job.Ch[z] = prh + (size_t)z * TSZ;
        job.Cl[z] = prl + (size_t)z * TSZ;
    }
    job.bias[0] = bq; job.bias[1] = bk; job.bias[2] = bv;

    dim3 ggrid(DMODEL / 256, NTOK / 128, 3);   // (4, 32, 3)
    gemm_mma_qkv<<<ggrid, 256, GEMM_SMEM>>>(job);

    const size_t OUTE  = (size_t)NTOK * DMODEL;
    const size_t ATTNE = (size_t)BATCH * NHEADS * SEQ * SEQ;
    float* outp  = (float*)d_out;
    float* attnp = ((size_t)out_size >= OUTE + ATTNE) ? (outp + OUTE) : nullptr;

    dim3 agrid(SEQ / 64, NHEADS, BATCH);
    attn_mma<<<agrid, 256, ATTN_SMEM_B>>>(attnp);

    dim3 ogrid(DMODEL / 256, NTOK / 128);      // (4, 32)
    gemm_mma_one<<<ogrid, 256, GEMM_SMEM>>>(ctx, wth + 3 * WSZ, wtl + 3 * WSZ, bo, outp);
}

// round 16
// speedup vs baseline: 1.1549x; 1.1549x over previous
#include <cuda_runtime.h>
#include <cuda_bf16.h>
#include <math.h>
#include <stdint.h>

#define BATCH  2
#define SEQ    2048
#define DMODEL 1024
#define NHEADS 16
#define DK     64
#define WIN    256
#define NTOK   (BATCH * SEQ)
#define TSZ    (NTOK * DMODEL)

// -------- scratch (allocation-free rule: __device__ globals) --------
__device__ __nv_bfloat16 g_pr_hi[3 * TSZ];   // projected Q,K,V split
__device__ __nv_bfloat16 g_pr_lo[3 * TSZ];
__device__ float         g_ctx[TSZ];         // attention ctx (fp32)
__device__ __nv_bfloat16 g_wt_hi[4 * DMODEL * DMODEL];  // W^T split
__device__ __nv_bfloat16 g_wt_lo[4 * DMODEL * DMODEL];

// -------- helpers --------
__device__ __forceinline__ uint32_t s2u(const void* p) {
    uint32_t a;
    asm("{ .reg .u64 t; cvta.to.shared.u64 t, %1; cvt.u32.u64 %0, t; }"
        : "=r"(a) : "l"(p));
    return a;
}
__device__ __forceinline__ void ldmx4(uint32_t* r, uint32_t addr) {
    asm volatile("ldmatrix.sync.aligned.m8n8.x4.shared.b16 {%0,%1,%2,%3}, [%4];"
                 : "=r"(r[0]), "=r"(r[1]), "=r"(r[2]), "=r"(r[3]) : "r"(addr));
}
__device__ __forceinline__ void ldmx4t(uint32_t* r, uint32_t addr) {
    asm volatile("ldmatrix.sync.aligned.m8n8.x4.trans.shared.b16 {%0,%1,%2,%3}, [%4];"
                 : "=r"(r[0]), "=r"(r[1]), "=r"(r[2]), "=r"(r[3]) : "r"(addr));
}
__device__ __forceinline__ void mma_bf16(float* c, const uint32_t* a, const uint32_t* b) {
    asm volatile(
        "mma.sync.aligned.m16n8k16.row.col.f32.bf16.bf16.f32 "
        "{%0,%1,%2,%3}, {%4,%5,%6,%7}, {%8,%9}, {%0,%1,%2,%3};"
        : "+f"(c[0]), "+f"(c[1]), "+f"(c[2]), "+f"(c[3])
        : "r"(a[0]), "r"(a[1]), "r"(a[2]), "r"(a[3]), "r"(b[0]), "r"(b[1]));
}
#define CP_ASYNC16(dst, src) \
    asm volatile("cp.async.ca.shared.global [%0], [%1], 16;" :: "r"(dst), "l"(src))
#define CP_ASYNC16CG(dst, src) \
    asm volatile("cp.async.cg.shared.global [%0], [%1], 16;" :: "r"(dst), "l"(src))
#define CP_ASYNC16CG_Z(dst, src, sz) \
    asm volatile("cp.async.cg.shared.global [%0], [%1], 16, %2;" :: "r"(dst), "l"(src), "r"(sz))
#define CP_COMMIT()  asm volatile("cp.async.commit_group;" ::: "memory")
#define CP_WAIT0()   asm volatile("cp.async.wait_group 0;" ::: "memory")
#define CP_WAIT1()   asm volatile("cp.async.wait_group 1;" ::: "memory")

__device__ __forceinline__ uint32_t hi_pack(float a, float b) {
    return __byte_perm(__float_as_uint(a), __float_as_uint(b), 0x7632);
}
__device__ __forceinline__ uint32_t lo_pack(float a, float b) {
    float ra = a - __uint_as_float(__float_as_uint(a) & 0xffff0000u);
    float rb = b - __uint_as_float(__float_as_uint(b) & 0xffff0000u);
    __nv_bfloat162 p = __floats2bfloat162_rn(ra, rb);
    return *(uint32_t*)&p;
}

// ==================== weight prep: Wt[n,k] = W[k,n], split hi/lo ====================
struct WPrep { const float* w[4]; };

__global__ __launch_bounds__(256)
void prep_w(WPrep wp, __nv_bfloat16* __restrict__ hi, __nv_bfloat16* __restrict__ lo) {
    __shared__ float t[32][33];
    const int wi = blockIdx.z;
    const float* W = wp.w[wi];
    const int n0 = blockIdx.x * 32, k0 = blockIdx.y * 32;
    const int tx = threadIdx.x & 31, ty = (threadIdx.x >> 5) * 4;
    #pragma unroll
    for (int i = 0; i < 4; i++)
        t[ty + i][tx] = W[(size_t)(k0 + ty + i) * DMODEL + n0 + tx];
    __syncthreads();
    #pragma unroll
    for (int i = 0; i < 4; i++) {
        float a = t[tx][ty + i];
        __nv_bfloat16 h = __float2bfloat16_rz(a);
        float hf = __bfloat162float(h);
        __nv_bfloat16 l = __float2bfloat16(a - hf);
        size_t idx = (size_t)wi * DMODEL * DMODEL + (size_t)(n0 + ty + i) * DMODEL + k0 + tx;
        hi[idx] = h;
        lo[idx] = l;
    }
}

// ==================== HMMA split-bf16 GEMM (R11 body; A-LDG first, B via .cg) ====================
struct GemmJob {
    const float* A[3];
    const __nv_bfloat16* Bh[3];
    const __nv_bfloat16* Bl[3];
    const float* bias[3];
    __nv_bfloat16 *Ch[3], *Cl[3];
};

template <bool BF16OUT>
__device__ __forceinline__
void gemm_mma_body(const float* __restrict__ A, const __nv_bfloat16* __restrict__ Bh,
                   const __nv_bfloat16* __restrict__ Bl, const float* __restrict__ bias,
                   float* __restrict__ C, __nv_bfloat16* __restrict__ Ch,
                   __nv_bfloat16* __restrict__ Cl) {
    extern __shared__ char smx[];
    const int tid = threadIdx.x, lane = tid & 31, wid = tid >> 5;
    const int brow = blockIdx.y << 7, bcol = blockIdx.x << 7;
    const int wm = (wid >> 2) << 6;
    const int wn = (wid & 3) << 5;

    const uint32_t sbase = s2u(smx);

    float acc[4][4][4];
    #pragma unroll
    for (int i = 0; i < 4; i++)
        #pragma unroll
        for (int j = 0; j < 4; j++)
            #pragma unroll
            for (int u = 0; u < 4; u++) acc[i][j][u] = 0.f;

    {
        #pragma unroll
        for (int it = 0; it < 2; it++) {
            int f = tid + it * 256;
            int row = f >> 2, grp = f & 3;
            const __nv_bfloat16* srcH = Bh + (size_t)(bcol + row) * DMODEL + grp * 8;
            const __nv_bfloat16* srcL = Bl + (size_t)(bcol + row) * DMODEL + grp * 8;
            uint32_t dH = sbase + 16384u + row * 128 + ((grp ^ (row & 7)) << 4);
            uint32_t dL = sbase + 16384u + row * 128 + (((grp + 4) ^ (row & 7)) << 4);
            CP_ASYNC16CG(dH, srcH);
            CP_ASYNC16CG(dL, srcL);
        }
        CP_COMMIT();
        #pragma unroll
        for (int it = 0; it < 2; it++) {
            int f = tid + it * 256;
            int row = f >> 2, grp = f & 3;
            const float* ap = A + (size_t)(brow + row) * DMODEL + grp * 8;
            float4 f0 = *(const float4*)ap, f1 = *(const float4*)(ap + 4);
            uint4 ah = make_uint4(hi_pack(f0.x, f0.y), hi_pack(f0.z, f0.w),
                                  hi_pack(f1.x, f1.y), hi_pack(f1.z, f1.w));
            uint4 al = make_uint4(lo_pack(f0.x, f0.y), lo_pack(f0.z, f0.w),
                                  lo_pack(f1.x, f1.y), lo_pack(f1.z, f1.w));
            *(uint4*)(smx + row * 128 + ((grp ^ (row & 7)) << 4)) = ah;
            *(uint4*)(smx + row * 128 + (((grp + 4) ^ (row & 7)) << 4)) = al;
        }
        CP_WAIT0();
        __syncthreads();
    }

    for (int kt = 0; kt < 32; kt++) {
        const int s = kt & 1;
        const uint32_t soff = (uint32_t)s << 15;

        float4 pf[2][2];
        if (kt < 31) {
            const int k0 = (kt + 1) << 5;
            const uint32_t noff = (uint32_t)(s ^ 1) << 15;
            // A LDGs first: longest-latency ops get the earliest issue
            #pragma unroll
            for (int it = 0; it < 2; it++) {
                int f = tid + it * 256;
                int row = f >> 2;
                const float* ap = A + (size_t)(brow + row) * DMODEL + k0 + (f & 3) * 8;
                pf[it][0] = *(const float4*)ap;
                pf[it][1] = *(const float4*)(ap + 4);
            }
            #pragma unroll
            for (int it = 0; it < 2; it++) {
                int f = tid + it * 256;
                int row = f >> 2, grp = f & 3;
                const __nv_bfloat16* srcH = Bh + (size_t)(bcol + row) * DMODEL + k0 + grp * 8;
                const __nv_bfloat16* srcL = Bl + (size_t)(bcol + row) * DMODEL + k0 + grp * 8;
                uint32_t dH = sbase + noff + 16384u + row * 128 + ((grp ^ (row & 7)) << 4);
                uint32_t dL = sbase + noff + 16384u + row * 128 + (((grp + 4) ^ (row & 7)) << 4);
                CP_ASYNC16CG(dH, srcH);
                CP_ASYNC16CG(dL, srcL);
            }
            CP_COMMIT();
        }

        const uint32_t aBase = sbase + soff;
        const uint32_t bBase = sbase + soff + 16384u;
        #pragma unroll
        for (int ks2 = 0; ks2 < 2; ks2++) {
            uint32_t aH[4][4], aL[4][4];
            const int cA = (ks2 << 1) + (lane >> 4);
            #pragma unroll
            for (int i = 0; i < 4; i++) {
                int r = wm + i * 16 + (lane & 15);
                ldmx4(aH[i], aBase + r * 128 + ((cA ^ (r & 7)) << 4));
                ldmx4(aL[i], aBase + r * 128 + (((cA + 4) ^ (r & 7)) << 4));
            }
            const int cB = (ks2 << 1) + ((lane >> 3) & 1);
            #pragma unroll
            for (int jp = 0; jp < 2; jp++) {
                int rn = wn + jp * 16 + (lane & 7) + ((lane >> 4) & 1) * 8;
                uint32_t bh4[4], bl4[4];
                ldmx4(bh4, bBase + rn * 128 + ((cB ^ (rn & 7)) << 4));
                ldmx4(bl4, bBase + rn * 128 + (((cB + 4) ^ (rn & 7)) << 4));
                #pragma unroll
                for (int i = 0; i < 4; i++) {
                    mma_bf16(acc[i][jp * 2], aH[i], bh4);
                    mma_bf16(acc[i][jp * 2], aH[i], bl4);
                    mma_bf16(acc[i][jp * 2], aL[i], bh4);
                    mma_bf16(acc[i][jp * 2 + 1], aH[i], bh4 + 2);
                    mma_bf16(acc[i][jp * 2 + 1], aH[i], bl4 + 2);
                    mma_bf16(acc[i][jp * 2 + 1], aL[i], bh4 + 2);
                }
            }
        }

        if (kt < 31) {
            const uint32_t noff = (uint32_t)(s ^ 1) << 15;
            #pragma unroll
            for (int it = 0; it < 2; it++) {
                int f = tid + it * 256;
                int row = f >> 2, grp = f & 3;
                float4 f0 = pf[it][0], f1 = pf[it][1];
                uint4 ah = make_uint4(hi_pack(f0.x, f0.y), hi_pack(f0.z, f0.w),
                                      hi_pack(f1.x, f1.y), hi_pack(f1.z, f1.w));
                uint4 al = make_uint4(lo_pack(f0.x, f0.y), lo_pack(f0.z, f0.w),
                                      lo_pack(f1.x, f1.y), lo_pack(f1.z, f1.w));
                *(uint4*)(smx + noff + row * 128 + ((grp ^ (row & 7)) << 4)) = ah;
                *(uint4*)(smx + noff + row * 128 + (((grp + 4) ^ (row & 7)) << 4)) = al;
            }
            CP_WAIT0();
        }
        __syncthreads();
    }

    const int g = lane >> 2, tg = lane & 3;
    #pragma unroll
    for (int i = 0; i < 4; i++) {
        const int r0 = brow + wm + i * 16 + g;
        #pragma unroll
        for (int j = 0; j < 4; j++) {
            const int col = bcol + wn + j * 8 + tg * 2;
            float2 bb = *(const float2*)(bias + col);
            float v0 = acc[i][j][0] + bb.x, v1 = acc[i][j][1] + bb.y;
            float v2 = acc[i][j][2] + bb.x, v3 = acc[i][j][3] + bb.y;
            if (BF16OUT) {
                *(uint32_t*)(Ch + (size_t)r0 * DMODEL + col)       = hi_pack(v0, v1);
                *(uint32_t*)(Cl + (size_t)r0 * DMODEL + col)       = lo_pack(v0, v1);
                *(uint32_t*)(Ch + (size_t)(r0 + 8) * DMODEL + col) = hi_pack(v2, v3);
                *(uint32_t*)(Cl + (size_t)(r0 + 8) * DMODEL + col) = lo_pack(v2, v3);
            } else {
                *(float2*)(C + (size_t)r0 * DMODEL + col)       = make_float2(v0, v1);
                *(float2*)(C + (size_t)(r0 + 8) * DMODEL + col) = make_float2(v2, v3);
            }
        }
    }
}

__global__ __launch_bounds__(256, 2)
void gemm_mma_qkv(GemmJob job) {
    const int z = blockIdx.z;
    gemm_mma_body<true>(job.A[z], job.Bh[z], job.Bl[z], job.bias[z],
                        nullptr, job.Ch[z], job.Cl[z]);
}

__global__ __launch_bounds__(256, 2)
void gemm_mma_one(const float* __restrict__ A, const __nv_bfloat16* __restrict__ Bh,
                  const __nv_bfloat16* __restrict__ Bl, const float* __restrict__ bias,
                  float* __restrict__ C) {
    gemm_mma_body<false>(A, Bh, Bl, bias, C, nullptr, nullptr);
}

// ==================== HMMA sliding-window attention (R11; K/V via .cg) ====================
#define SQH 0
#define SQL 8192
#define SKH 16384
#define SKL 32768
#define SVH 49152
#define SVL 65536
#define SMP 81920
#define SLP 82432
#define ATTN_SMEM_B 83968

__device__ __forceinline__
void attn_cp128(const __nv_bfloat16* __restrict__ Hsrc, const __nv_bfloat16* __restrict__ Lsrc,
                uint32_t dhi, uint32_t dlo, int kbase, int hi_local, int tid) {
    #pragma unroll
    for (int it = 0; it < 8; it++) {
        int f = tid + it * 256;
        int buf = f >> 10;
        int rr = (f >> 3) & 127;
        int gr = f & 7;
        int kr = kbase + rr;
        uint32_t sz = (kr <= hi_local) ? 16u : 0u;
        int srow = (kr <= hi_local) ? kr : hi_local;
        const __nv_bfloat16* s = (buf ? Lsrc : Hsrc) + (size_t)srow * DMODEL + gr * 8;
        uint32_t d = (buf ? dlo : dhi) + rr * 128 + ((gr ^ (rr & 7)) << 4);
        CP_ASYNC16CG_Z(d, s, sz);
    }
}

__device__ __forceinline__
void qk_mma(float acc[8][4], uint32_t qh, uint32_t ql, uint32_t kh, uint32_t kl,
            int wm, int wnh, int lane) {
    #pragma unroll
    for (int j = 0; j < 8; j++)
        #pragma unroll
        for (int u = 0; u < 4; u++) acc[j][u] = 0.f;
    #pragma unroll
    for (int ks = 0; ks < 4; ks++) {
        uint32_t aH[4], aL[4];
        int ar = wm + (lane & 15);
        int cA = ks * 2 + (lane >> 4);
        uint32_t aoff = ar * 128 + ((cA ^ (ar & 7)) << 4);
        ldmx4(aH, qh + aoff);
        ldmx4(aL, ql + aoff);
        int cB = ks * 2 + ((lane >> 3) & 1);
        #pragma unroll
        for (int jp = 0; jp < 4; jp++) {
            int rn = wnh * 64 + jp * 16 + (lane & 7) + ((lane >> 4) & 1) * 8;
            uint32_t boff = rn * 128 + ((cB ^ (rn & 7)) << 4);
            uint32_t bh4[4], bl4[4];
            ldmx4(bh4, kh + boff);
            ldmx4(bl4, kl + boff);
            mma_bf16(acc[jp * 2], aH, bh4);
            mma_bf16(acc[jp * 2], aH, bl4);
            mma_bf16(acc[jp * 2], aL, bh4);
            mma_bf16(acc[jp * 2 + 1], aH, bh4 + 2);
            mma_bf16(acc[jp * 2 + 1], aH, bl4 + 2);
            mma_bf16(acc[jp * 2 + 1], aL, bh4 + 2);
        }
    }
}

__global__ __launch_bounds__(256, 2)
void attn_mma(float* __restrict__ attnp) {
    extern __shared__ char sax[];
    float* sMp = (float*)(sax + SMP);
    float* sLp = (float*)(sax + SLP);

    const int qt = blockIdx.x, h = blockIdx.y, b = blockIdx.z;
    const int q0 = qt * 64;
    const int tid = threadIdx.x, lane = tid & 31, w = tid >> 5;
    const int wm = (w >> 1) << 4;
    const int wnh = w & 1;
    const int g = lane >> 2, tg = lane & 3;

    const int lo  = max(0, q0 - WIN);
    const int hi  = min(SEQ - 1, q0 + 63 + WIN);
    const int cnt = hi - lo + 1;
    const int nch = (cnt + 127) >> 7;

    const uint32_t qh = s2u(sax) + SQH, ql = s2u(sax) + SQL;
    const uint32_t kh = s2u(sax) + SKH, kl = s2u(sax) + SKL;
    const uint32_t vh = s2u(sax) + SVH, vl = s2u(sax) + SVL;

    const size_t hoff = (size_t)(b * SEQ) * DMODEL + h * DK;
    const __nv_bfloat16* Qh = g_pr_hi + hoff;
    const __nv_bfloat16* Ql = g_pr_lo + hoff;
    const __nv_bfloat16* Kh = g_pr_hi + TSZ + hoff;
    const __nv_bfloat16* Kl = g_pr_lo + TSZ + hoff;
    const __nv_bfloat16* Vh = g_pr_hi + 2 * (size_t)TSZ + hoff;
    const __nv_bfloat16* Vl = g_pr_lo + 2 * (size_t)TSZ + hoff;

    // ---- Q tile via cp.async ----
    #pragma unroll
    for (int it = 0; it < 4; it++) {
        int f = tid + it * 256;
        int buf = f >> 9;
        int rr = (f >> 3) & 63;
        int gr = f & 7;
        const __nv_bfloat16* s = (buf ? Ql : Qh) + (size_t)(q0 + rr) * DMODEL + gr * 8;
        uint32_t d = (buf ? ql : qh) + rr * 128 + ((gr ^ (rr & 7)) << 4);
        CP_ASYNC16(d, s);
    }
    CP_COMMIT();

    const int qg0 = q0 + wm + g, qg1 = qg0 + 8;
    const int jlo0 = max(lo, qg0 - WIN), jhi0 = min(hi, qg0 + WIN);
    const int jlo1 = max(lo, qg1 - WIN), jhi1 = min(hi, qg1 + WIN);

    // ---- pass 1: online (m, l), K double-buffered across (kh,kl)/(vh,vl) ----
    attn_cp128(Kh, Kl, kh, kl, lo, hi, tid);
    CP_COMMIT();

    float m0 = -1e30f, m1 = -1e30f, l0 = 0.f, l1 = 0.f;
    for (int c = 0; c < nch; c++) {
        if (c + 1 < nch) {
            uint32_t dh = ((c + 1) & 1) ? vh : kh;
            uint32_t dl = ((c + 1) & 1) ? vl : kl;
            attn_cp128(Kh, Kl, dh, dl, lo + (c + 1) * 128, hi, tid);
            CP_COMMIT();
            CP_WAIT1();
        } else {
            CP_WAIT0();
        }
        __syncthreads();

        uint32_t ch_ = (c & 1) ? vh : kh;
        uint32_t cl_ = (c & 1) ? vl : kl;
        float acc[8][4];
        qk_mma(acc, qh, ql, ch_, cl_, wm, wnh, lane);

        const int cb = lo + c * 128 + wnh * 64;
        float cmax0 = -1e30f, cmax1 = -1e30f;
        #pragma unroll
        for (int j = 0; j < 8; j++) {
            int jg = cb + j * 8 + tg * 2;
            #pragma unroll
            for (int u = 0; u < 4; u++) acc[j][u] *= 0.125f;
            if (jg     >= jlo0 && jg     <= jhi0) cmax0 = fmaxf(cmax0, acc[j][0]);
            if (jg + 1 >= jlo0 && jg + 1 <= jhi0) cmax0 = fmaxf(cmax0, acc[j][1]);
            if (jg     >= jlo1 && jg     <= jhi1) cmax1 = fmaxf(cmax1, acc[j][2]);
            if (jg + 1 >= jlo1 && jg + 1 <= jhi1) cmax1 = fmaxf(cmax1, acc[j][3]);
        }
        cmax0 = fmaxf(cmax0, __shfl_xor_sync(0xffffffffu, cmax0, 1));
        cmax0 = fmaxf(cmax0, __shfl_xor_sync(0xffffffffu, cmax0, 2));
        cmax1 = fmaxf(cmax1, __shfl_xor_sync(0xffffffffu, cmax1, 1));
        cmax1 = fmaxf(cmax1, __shfl_xor_sync(0xffffffffu, cmax1, 2));

        float mn0 = fmaxf(m0, cmax0), mn1 = fmaxf(m1, cmax1);
        float s0 = 0.f, s1 = 0.f;
        #pragma unroll
        for (int j = 0; j < 8; j++) {
            int jg = cb + j * 8 + tg * 2;
            if (jg     >= jlo0 && jg     <= jhi0) s0 += __expf(acc[j][0] - mn0);
            if (jg + 1 >= jlo0 && jg + 1 <= jhi0) s0 += __expf(acc[j][1] - mn0);
            if (jg     >= jlo1 && jg     <= jhi1) s1 += __expf(acc[j][2] - mn1);
            if (jg + 1 >= jlo1 && jg + 1 <= jhi1) s1 += __expf(acc[j][3] - mn1);
        }
        s0 += __shfl_xor_sync(0xffffffffu, s0, 1);
        s0 += __shfl_xor_sync(0xffffffffu, s0, 2);
        s1 += __shfl_xor_sync(0xffffffffu, s1, 1);
        s1 += __shfl_xor_sync(0xffffffffu, s1, 2);

        l0 = (m0 > -1e29f ? l0 * __expf(m0 - mn0) : 0.f) + s0;
        l1 = (m1 > -1e29f ? l1 * __expf(m1 - mn1) : 0.f) + s1;
        m0 = mn0; m1 = mn1;
        __syncthreads();
    }

    // ---- merge halves; prefetch pass-2 chunk 0 under the merge ----
    if (tg == 0) {
        sMp[wnh * 64 + wm + g]     = m0;  sLp[wnh * 64 + wm + g]     = l0;
        sMp[wnh * 64 + wm + g + 8] = m1;  sLp[wnh * 64 + wm + g + 8] = l1;
    }
    attn_cp128(Kh, Kl, kh, kl, lo, hi, tid);
    attn_cp128(Vh, Vl, vh, vl, lo, hi, tid);
    CP_COMMIT();
    __syncthreads();

    float mf0, mf1, li0, li1;
    {
        int r0 = wm + g, r1 = r0 + 8;
        float ma = sMp[r0], mb2 = sMp[64 + r0];
        float la = sLp[r0], lb2 = sLp[64 + r0];
        mf0 = fmaxf(ma, mb2);
        li0 = 1.f / (la * __expf(ma - mf0) + lb2 * __expf(mb2 - mf0));
        ma = sMp[r1]; mb2 = sMp[64 + r1];
        la = sLp[r1]; lb2 = sLp[64 + r1];
        mf1 = fmaxf(ma, mb2);
        li1 = 1.f / (la * __expf(ma - mf1) + lb2 * __expf(mb2 - mf1));
    }

    float* baseA = nullptr;
    if (attnp) {
        baseA = attnp + ((size_t)((b * NHEADS + h) * SEQ + q0)) * SEQ;
        const int z2 = min((int)SEQ, lo + nch * 128);
        for (int f = tid; f < 64 * 512; f += 256) {
            int m = f >> 9, c4 = (f & 511) << 2;
            if (c4 < lo || c4 >= z2)
                *(float4*)(baseA + (size_t)m * SEQ + c4) = make_float4(0.f, 0.f, 0.f, 0.f);
        }
    }

    // ---- pass 2 ----
    float oacc[4][4];
    #pragma unroll
    for (int j = 0; j < 4; j++)
        #pragma unroll
        for (int u = 0; u < 4; u++) oacc[j][u] = 0.f;

    for (int c = 0; c < nch; c++) {
        CP_WAIT0();
        __syncthreads();
        float acc[8][4];
        qk_mma(acc, qh, ql, kh, kl, wm, wnh, lane);

        const int cb = lo + c * 128 + wnh * 64;
        #pragma unroll
        for (int j = 0; j < 8; j++) {
            int jg = cb + j * 8 + tg * 2;
            float p0 = (jg     >= jlo0 && jg     <= jhi0) ? __expf(acc[j][0] * 0.125f - mf0) * li0 : 0.f;
            float p1 = (jg + 1 >= jlo0 && jg + 1 <= jhi0) ? __expf(acc[j][1] * 0.125f - mf0) * li0 : 0.f;
            float p2 = (jg     >= jlo1 && jg     <= jhi1) ? __expf(acc[j][2] * 0.125f - mf1) * li1 : 0.f;
            float p3 = (jg + 1 >= jlo1 && jg + 1 <= jhi1) ? __expf(acc[j][3] * 0.125f - mf1) * li1 : 0.f;
            acc[j][0] = p0; acc[j][1] = p1; acc[j][2] = p2; acc[j][3] = p3;
            if (baseA && jg < SEQ) {
                *(float2*)(baseA + (size_t)(wm + g) * SEQ + jg)     = make_float2(p0, p1);
                *(float2*)(baseA + (size_t)(wm + g + 8) * SEQ + jg) = make_float2(p2, p3);
            }
        }
        __syncthreads();

        #pragma unroll
        for (int j = 0; j < 8; j++) {
            int col = wnh * 64 + j * 8 + tg * 2;
            int sub = col >> 6, c64 = col & 63;
            int r0 = wm + g, r1 = r0 + 8;
            int o0 = sub * 8192 + r0 * 128 + ((((c64 >> 3)) ^ (r0 & 7)) << 4) + (c64 & 7) * 2;
            int o1 = sub * 8192 + r1 * 128 + ((((c64 >> 3)) ^ (r1 & 7)) << 4) + (c64 & 7) * 2;
            *(uint32_t*)(sax + SKH + o0) = hi_pack(acc[j][0], acc[j][1]);
            *(uint32_t*)(sax + SKL + o0) = lo_pack(acc[j][0], acc[j][1]);
            *(uint32_t*)(sax + SKH + o1) = hi_pack(acc[j][2], acc[j][3]);
            *(uint32_t*)(sax + SKL + o1) = lo_pack(acc[j][2], acc[j][3]);
        }
        __syncthreads();

        #pragma unroll
        for (int ks = 0; ks < 8; ks++) {
            uint32_t aH[4], aL[4];
            int ar = wm + (lane & 15);
            int sub = ks >> 2;
            int cA = (ks & 3) * 2 + (lane >> 4);
            uint32_t aoff = sub * 8192 + ar * 128 + ((cA ^ (ar & 7)) << 4);
            ldmx4(aH, kh + aoff);
            ldmx4(aL, kl + aoff);
            #pragma unroll
            for (int jp = 0; jp < 2; jp++) {
                int rv = ks * 16 + (lane & 15);
                int gd = wnh * 4 + jp * 2 + (lane >> 4);
                uint32_t boff = rv * 128 + ((gd ^ (rv & 7)) << 4);
                uint32_t vh4[4], vl4[4];
                ldmx4t(vh4, vh + boff);
                ldmx4t(vl4, vl + boff);
                mma_bf16(oacc[jp * 2], aH, vh4);
                mma_bf16(oacc[jp * 2], aH, vl4);
                mma_bf16(oacc[jp * 2], aL, vh4);
                mma_bf16(oacc[jp * 2 + 1], aH, vh4 + 2);
                mma_bf16(oacc[jp * 2 + 1], aH, vl4 + 2);
                mma_bf16(oacc[jp * 2 + 1], aL, vh4 + 2);
            }
        }

        if (c + 1 < nch) {
            __syncthreads();
            attn_cp128(Kh, Kl, kh, kl, lo + (c + 1) * 128, hi, tid);
            attn_cp128(Vh, Vl, vh, vl, lo + (c + 1) * 128, hi, tid);
            CP_COMMIT();
        }
    }

    // ---- write ctx (fp32, feeds O-proj) ----
    {
        float* cb2 = g_ctx + ((size_t)(b * SEQ + q0 + wm + g)) * DMODEL + h * DK + wnh * 32;
        #pragma unroll
        for (int j = 0; j < 4; j++) {
            int col = j * 8 + tg * 2;
            *(float2*)(cb2 + col)              = make_float2(oacc[j][0], oacc[j][1]);
            *(float2*)(cb2 + 8 * DMODEL + col) = make_float2(oacc[j][2], oacc[j][3]);
        }
    }
}

// ==================== launch ====================
extern "C" void kernel_launch(void* const* d_in, const int* in_sizes, int n_in,
                              void* d_out, int out_size) {
    const float* q  = (const float*)d_in[0];
    const float* k  = (const float*)d_in[1];
    const float* v  = (const float*)d_in[2];
    const float* Wq = (const float*)d_in[3];
    const float* bq = (const float*)d_in[4];
    const float* Wk = (const float*)d_in[5];
    const float* bk = (const float*)d_in[6];
    const float* Wv = (const float*)d_in[7];
    const float* bv = (const float*)d_in[8];
    const float* Wo = (const float*)d_in[9];
    const float* bo = (const float*)d_in[10];

    __nv_bfloat16 *prh, *prl, *wth, *wtl;
    float* ctx;
    cudaGetSymbolAddress((void**)&prh, g_pr_hi);
    cudaGetSymbolAddress((void**)&prl, g_pr_lo);
    cudaGetSymbolAddress((void**)&ctx, g_ctx);
    cudaGetSymbolAddress((void**)&wth, g_wt_hi);
    cudaGetSymbolAddress((void**)&wtl, g_wt_lo);

    const int GEMM_SMEM = 2 * 32768;
    cudaFuncSetAttribute(gemm_mma_qkv, cudaFuncAttributeMaxDynamicSharedMemorySize, GEMM_SMEM);
    cudaFuncSetAttribute(gemm_mma_one, cudaFuncAttributeMaxDynamicSharedMemorySize, GEMM_SMEM);
    cudaFuncSetAttribute(attn_mma, cudaFuncAttributeMaxDynamicSharedMemorySize, ATTN_SMEM_B);

    WPrep wp;
    wp.w[0] = Wq; wp.w[1] = Wk; wp.w[2] = Wv; wp.w[3] = Wo;
    dim3 pgrid(DMODEL / 32, DMODEL / 32, 4);
    prep_w<<<pgrid, 256>>>(wp, wth, wtl);

    GemmJob job;
    const size_t WSZ = (size_t)DMODEL * DMODEL;
    job.A[0] = q;  job.A[1] = k;  job.A[2] = v;
    for (int z = 0; z < 3; z++) {
        job.Bh[z] = wth + (size_t)z * WSZ;
        job.Bl[z] = wtl + (size_t)z * WSZ;
        job.Ch[z] = prh + (size_t)z * TSZ;
        job.Cl[z] = prl + (size_t)z * TSZ;
    }
    job.bias[0] = bq; job.bias[1] = bk; job.bias[2] = bv;

    dim3 ggrid(DMODEL / 128, NTOK / 128, 3);
    gemm_mma_qkv<<<ggrid, 256, GEMM_SMEM>>>(job);

    const size_t OUTE  = (size_t)NTOK * DMODEL;
    const size_t ATTNE = (size_t)BATCH * NHEADS * SEQ * SEQ;
    float* outp  = (float*)d_out;
    float* attnp = ((size_t)out_size >= OUTE + ATTNE) ? (outp + OUTE) : nullptr;

    dim3 agrid(SEQ / 64, NHEADS, BATCH);
    attn_mma<<<agrid, 256, ATTN_SMEM_B>>>(attnp);

    dim3 ogrid(DMODEL / 128, NTOK / 128);
    gemm_mma_one<<<ogrid, 256, GEMM_SMEM>>>(ctx, wth + 3 * WSZ, wtl + 3 * WSZ, bo, outp);
}

// round 17
// speedup vs baseline: 1.1684x; 1.0116x over previous
#include <cuda_runtime.h>
#include <cuda_bf16.h>
#include <math.h>
#include <stdint.h>

#define BATCH  2
#define SEQ    2048
#define DMODEL 1024
#define NHEADS 16
#define DK     64
#define WIN    256
#define NTOK   (BATCH * SEQ)
#define TSZ    (NTOK * DMODEL)

// -------- scratch (allocation-free rule: __device__ globals) --------
__device__ __nv_bfloat16 g_pr_hi[3 * TSZ];   // projected Q,K,V split
__device__ __nv_bfloat16 g_pr_lo[3 * TSZ];
__device__ float         g_ctx[TSZ];         // attention ctx (fp32)
__device__ __nv_bfloat16 g_wt_hi[4 * DMODEL * DMODEL];  // W^T split
__device__ __nv_bfloat16 g_wt_lo[4 * DMODEL * DMODEL];

// -------- helpers --------
__device__ __forceinline__ uint32_t s2u(const void* p) {
    uint32_t a;
    asm("{ .reg .u64 t; cvta.to.shared.u64 t, %1; cvt.u32.u64 %0, t; }"
        : "=r"(a) : "l"(p));
    return a;
}
__device__ __forceinline__ void ldmx4(uint32_t* r, uint32_t addr) {
    asm volatile("ldmatrix.sync.aligned.m8n8.x4.shared.b16 {%0,%1,%2,%3}, [%4];"
                 : "=r"(r[0]), "=r"(r[1]), "=r"(r[2]), "=r"(r[3]) : "r"(addr));
}
__device__ __forceinline__ void ldmx4t(uint32_t* r, uint32_t addr) {
    asm volatile("ldmatrix.sync.aligned.m8n8.x4.trans.shared.b16 {%0,%1,%2,%3}, [%4];"
                 : "=r"(r[0]), "=r"(r[1]), "=r"(r[2]), "=r"(r[3]) : "r"(addr));
}
__device__ __forceinline__ void mma_bf16(float* c, const uint32_t* a, const uint32_t* b) {
    asm volatile(
        "mma.sync.aligned.m16n8k16.row.col.f32.bf16.bf16.f32 "
        "{%0,%1,%2,%3}, {%4,%5,%6,%7}, {%8,%9}, {%0,%1,%2,%3};"
        : "+f"(c[0]), "+f"(c[1]), "+f"(c[2]), "+f"(c[3])
        : "r"(a[0]), "r"(a[1]), "r"(a[2]), "r"(a[3]), "r"(b[0]), "r"(b[1]));
}
#define CP_ASYNC16(dst, src) \
    asm volatile("cp.async.ca.shared.global [%0], [%1], 16;" :: "r"(dst), "l"(src))
#define CP_ASYNC16CG(dst, src) \
    asm volatile("cp.async.cg.shared.global [%0], [%1], 16;" :: "r"(dst), "l"(src))
#define CP_ASYNC16CG_Z(dst, src, sz) \
    asm volatile("cp.async.cg.shared.global [%0], [%1], 16, %2;" :: "r"(dst), "l"(src), "r"(sz))
#define CP_COMMIT()  asm volatile("cp.async.commit_group;" ::: "memory")
#define CP_WAIT0()   asm volatile("cp.async.wait_group 0;" ::: "memory")
#define CP_WAIT1()   asm volatile("cp.async.wait_group 1;" ::: "memory")

// streaming (evict-first) stores for never-re-read outputs
__device__ __forceinline__ void stcs4(float* p, float4 v) {
    asm volatile("st.global.cs.v4.f32 [%0], {%1,%2,%3,%4};"
                 :: "l"(p), "f"(v.x), "f"(v.y), "f"(v.z), "f"(v.w) : "memory");
}
__device__ __forceinline__ void stcs2(float* p, float2 v) {
    asm volatile("st.global.cs.v2.f32 [%0], {%1,%2};"
                 :: "l"(p), "f"(v.x), "f"(v.y) : "memory");
}

__device__ __forceinline__ uint32_t hi_pack(float a, float b) {
    return __byte_perm(__float_as_uint(a), __float_as_uint(b), 0x7632);
}
__device__ __forceinline__ uint32_t lo_pack(float a, float b) {
    float ra = a - __uint_as_float(__float_as_uint(a) & 0xffff0000u);
    float rb = b - __uint_as_float(__float_as_uint(b) & 0xffff0000u);
    __nv_bfloat162 p = __floats2bfloat162_rn(ra, rb);
    return *(uint32_t*)&p;
}

// ==================== weight prep: Wt[n,k] = W[k,n], split hi/lo ====================
struct WPrep { const float* w[4]; };

__global__ __launch_bounds__(256)
void prep_w(WPrep wp, __nv_bfloat16* __restrict__ hi, __nv_bfloat16* __restrict__ lo) {
    __shared__ float t[32][33];
    const int wi = blockIdx.z;
    const float* W = wp.w[wi];
    const int n0 = blockIdx.x * 32, k0 = blockIdx.y * 32;
    const int tx = threadIdx.x & 31, ty = (threadIdx.x >> 5) * 4;
    #pragma unroll
    for (int i = 0; i < 4; i++)
        t[ty + i][tx] = W[(size_t)(k0 + ty + i) * DMODEL + n0 + tx];
    __syncthreads();
    #pragma unroll
    for (int i = 0; i < 4; i++) {
        float a = t[tx][ty + i];
        __nv_bfloat16 h = __float2bfloat16_rz(a);
        float hf = __bfloat162float(h);
        __nv_bfloat16 l = __float2bfloat16(a - hf);
        size_t idx = (size_t)wi * DMODEL * DMODEL + (size_t)(n0 + ty + i) * DMODEL + k0 + tx;
        hi[idx] = h;
        lo[idx] = l;
    }
}

// ==================== HMMA split-bf16 GEMM (R16 body) ====================
struct GemmJob {
    const float* A[3];
    const __nv_bfloat16* Bh[3];
    const __nv_bfloat16* Bl[3];
    const float* bias[3];
    __nv_bfloat16 *Ch[3], *Cl[3];
};

template <bool BF16OUT>
__device__ __forceinline__
void gemm_mma_body(const float* __restrict__ A, const __nv_bfloat16* __restrict__ Bh,
                   const __nv_bfloat16* __restrict__ Bl, const float* __restrict__ bias,
                   float* __restrict__ C, __nv_bfloat16* __restrict__ Ch,
                   __nv_bfloat16* __restrict__ Cl) {
    extern __shared__ char smx[];
    const int tid = threadIdx.x, lane = tid & 31, wid = tid >> 5;
    const int brow = blockIdx.y << 7, bcol = blockIdx.x << 7;
    const int wm = (wid >> 2) << 6;
    const int wn = (wid & 3) << 5;

    const uint32_t sbase = s2u(smx);

    float acc[4][4][4];
    #pragma unroll
    for (int i = 0; i < 4; i++)
        #pragma unroll
        for (int j = 0; j < 4; j++)
            #pragma unroll
            for (int u = 0; u < 4; u++) acc[i][j][u] = 0.f;

    {
        #pragma unroll
        for (int it = 0; it < 2; it++) {
            int f = tid + it * 256;
            int row = f >> 2, grp = f & 3;
            const __nv_bfloat16* srcH = Bh + (size_t)(bcol + row) * DMODEL + grp * 8;
            const __nv_bfloat16* srcL = Bl + (size_t)(bcol + row) * DMODEL + grp * 8;
            uint32_t dH = sbase + 16384u + row * 128 + ((grp ^ (row & 7)) << 4);
            uint32_t dL = sbase + 16384u + row * 128 + (((grp + 4) ^ (row & 7)) << 4);
            CP_ASYNC16CG(dH, srcH);
            CP_ASYNC16CG(dL, srcL);
        }
        CP_COMMIT();
        #pragma unroll
        for (int it = 0; it < 2; it++) {
            int f = tid + it * 256;
            int row = f >> 2, grp = f & 3;
            const float* ap = A + (size_t)(brow + row) * DMODEL + grp * 8;
            float4 f0 = *(const float4*)ap, f1 = *(const float4*)(ap + 4);
            uint4 ah = make_uint4(hi_pack(f0.x, f0.y), hi_pack(f0.z, f0.w),
                                  hi_pack(f1.x, f1.y), hi_pack(f1.z, f1.w));
            uint4 al = make_uint4(lo_pack(f0.x, f0.y), lo_pack(f0.z, f0.w),
                                  lo_pack(f1.x, f1.y), lo_pack(f1.z, f1.w));
            *(uint4*)(smx + row * 128 + ((grp ^ (row & 7)) << 4)) = ah;
            *(uint4*)(smx + row * 128 + (((grp + 4) ^ (row & 7)) << 4)) = al;
        }
        CP_WAIT0();
        __syncthreads();
    }

    for (int kt = 0; kt < 32; kt++) {
        const int s = kt & 1;
        const uint32_t soff = (uint32_t)s << 15;

        float4 pf[2][2];
        if (kt < 31) {
            const int k0 = (kt + 1) << 5;
            const uint32_t noff = (uint32_t)(s ^ 1) << 15;
            #pragma unroll
            for (int it = 0; it < 2; it++) {
                int f = tid + it * 256;
                int row = f >> 2;
                const float* ap = A + (size_t)(brow + row) * DMODEL + k0 + (f & 3) * 8;
                pf[it][0] = *(const float4*)ap;
                pf[it][1] = *(const float4*)(ap + 4);
            }
            #pragma unroll
            for (int it = 0; it < 2; it++) {
                int f = tid + it * 256;
                int row = f >> 2, grp = f & 3;
                const __nv_bfloat16* srcH = Bh + (size_t)(bcol + row) * DMODEL + k0 + grp * 8;
                const __nv_bfloat16* srcL = Bl + (size_t)(bcol + row) * DMODEL + k0 + grp * 8;
                uint32_t dH = sbase + noff + 16384u + row * 128 + ((grp ^ (row & 7)) << 4);
                uint32_t dL = sbase + noff + 16384u + row * 128 + (((grp + 4) ^ (row & 7)) << 4);
                CP_ASYNC16CG(dH, srcH);
                CP_ASYNC16CG(dL, srcL);
            }
            CP_COMMIT();
        }

        const uint32_t aBase = sbase + soff;
        const uint32_t bBase = sbase + soff + 16384u;
        #pragma unroll
        for (int ks2 = 0; ks2 < 2; ks2++) {
            uint32_t aH[4][4], aL[4][4];
            const int cA = (ks2 << 1) + (lane >> 4);
            #pragma unroll
            for (int i = 0; i < 4; i++) {
                int r = wm + i * 16 + (lane & 15);
                ldmx4(aH[i], aBase + r * 128 + ((cA ^ (r & 7)) << 4));
                ldmx4(aL[i], aBase + r * 128 + (((cA + 4) ^ (r & 7)) << 4));
            }
            const int cB = (ks2 << 1) + ((lane >> 3) & 1);
            #pragma unroll
            for (int jp = 0; jp < 2; jp++) {
                int rn = wn + jp * 16 + (lane & 7) + ((lane >> 4) & 1) * 8;
                uint32_t bh4[4], bl4[4];
                ldmx4(bh4, bBase + rn * 128 + ((cB ^ (rn & 7)) << 4));
                ldmx4(bl4, bBase + rn * 128 + (((cB + 4) ^ (rn & 7)) << 4));
                #pragma unroll
                for (int i = 0; i < 4; i++) {
                    mma_bf16(acc[i][jp * 2], aH[i], bh4);
                    mma_bf16(acc[i][jp * 2], aH[i], bl4);
                    mma_bf16(acc[i][jp * 2], aL[i], bh4);
                    mma_bf16(acc[i][jp * 2 + 1], aH[i], bh4 + 2);
                    mma_bf16(acc[i][jp * 2 + 1], aH[i], bl4 + 2);
                    mma_bf16(acc[i][jp * 2 + 1], aL[i], bh4 + 2);
                }
            }
        }

        if (kt < 31) {
            const uint32_t noff = (uint32_t)(s ^ 1) << 15;
            #pragma unroll
            for (int it = 0; it < 2; it++) {
                int f = tid + it * 256;
                int row = f >> 2, grp = f & 3;
                float4 f0 = pf[it][0], f1 = pf[it][1];
                uint4 ah = make_uint4(hi_pack(f0.x, f0.y), hi_pack(f0.z, f0.w),
                                      hi_pack(f1.x, f1.y), hi_pack(f1.z, f1.w));
                uint4 al = make_uint4(lo_pack(f0.x, f0.y), lo_pack(f0.z, f0.w),
                                      lo_pack(f1.x, f1.y), lo_pack(f1.z, f1.w));
                *(uint4*)(smx + noff + row * 128 + ((grp ^ (row & 7)) << 4)) = ah;
                *(uint4*)(smx + noff + row * 128 + (((grp + 4) ^ (row & 7)) << 4)) = al;
            }
            CP_WAIT0();
        }
        __syncthreads();
    }

    const int g = lane >> 2, tg = lane & 3;
    #pragma unroll
    for (int i = 0; i < 4; i++) {
        const int r0 = brow + wm + i * 16 + g;
        #pragma unroll
        for (int j = 0; j < 4; j++) {
            const int col = bcol + wn + j * 8 + tg * 2;
            float2 bb = *(const float2*)(bias + col);
            float v0 = acc[i][j][0] + bb.x, v1 = acc[i][j][1] + bb.y;
            float v2 = acc[i][j][2] + bb.x, v3 = acc[i][j][3] + bb.y;
            if (BF16OUT) {
                *(uint32_t*)(Ch + (size_t)r0 * DMODEL + col)       = hi_pack(v0, v1);
                *(uint32_t*)(Cl + (size_t)r0 * DMODEL + col)       = lo_pack(v0, v1);
                *(uint32_t*)(Ch + (size_t)(r0 + 8) * DMODEL + col) = hi_pack(v2, v3);
                *(uint32_t*)(Cl + (size_t)(r0 + 8) * DMODEL + col) = lo_pack(v2, v3);
            } else {
                stcs2(C + (size_t)r0 * DMODEL + col,       make_float2(v0, v1));
                stcs2(C + (size_t)(r0 + 8) * DMODEL + col, make_float2(v2, v3));
            }
        }
    }
}

__global__ __launch_bounds__(256, 2)
void gemm_mma_qkv(GemmJob job) {
    const int z = blockIdx.z;
    gemm_mma_body<true>(job.A[z], job.Bh[z], job.Bl[z], job.bias[z],
                        nullptr, job.Ch[z], job.Cl[z]);
}

__global__ __launch_bounds__(256, 2)
void gemm_mma_one(const float* __restrict__ A, const __nv_bfloat16* __restrict__ Bh,
                  const __nv_bfloat16* __restrict__ Bl, const float* __restrict__ bias,
                  float* __restrict__ C) {
    gemm_mma_body<false>(A, Bh, Bl, bias, C, nullptr, nullptr);
}

// ==================== HMMA sliding-window attention (R16; .cs attn stores) ====================
#define SQH 0
#define SQL 8192
#define SKH 16384
#define SKL 32768
#define SVH 49152
#define SVL 65536
#define SMP 81920
#define SLP 82432
#define ATTN_SMEM_B 83968

__device__ __forceinline__
void attn_cp128(const __nv_bfloat16* __restrict__ Hsrc, const __nv_bfloat16* __restrict__ Lsrc,
                uint32_t dhi, uint32_t dlo, int kbase, int hi_local, int tid) {
    #pragma unroll
    for (int it = 0; it < 8; it++) {
        int f = tid + it * 256;
        int buf = f >> 10;
        int rr = (f >> 3) & 127;
        int gr = f & 7;
        int kr = kbase + rr;
        uint32_t sz = (kr <= hi_local) ? 16u : 0u;
        int srow = (kr <= hi_local) ? kr : hi_local;
        const __nv_bfloat16* s = (buf ? Lsrc : Hsrc) + (size_t)srow * DMODEL + gr * 8;
        uint32_t d = (buf ? dlo : dhi) + rr * 128 + ((gr ^ (rr & 7)) << 4);
        CP_ASYNC16CG_Z(d, s, sz);
    }
}

__device__ __forceinline__
void qk_mma(float acc[8][4], uint32_t qh, uint32_t ql, uint32_t kh, uint32_t kl,
            int wm, int wnh, int lane) {
    #pragma unroll
    for (int j = 0; j < 8; j++)
        #pragma unroll
        for (int u = 0; u < 4; u++) acc[j][u] = 0.f;
    #pragma unroll
    for (int ks = 0; ks < 4; ks++) {
        uint32_t aH[4], aL[4];
        int ar = wm + (lane & 15);
        int cA = ks * 2 + (lane >> 4);
        uint32_t aoff = ar * 128 + ((cA ^ (ar & 7)) << 4);
        ldmx4(aH, qh + aoff);
        ldmx4(aL, ql + aoff);
        int cB = ks * 2 + ((lane >> 3) & 1);
        #pragma unroll
        for (int jp = 0; jp < 4; jp++) {
            int rn = wnh * 64 + jp * 16 + (lane & 7) + ((lane >> 4) & 1) * 8;
            uint32_t boff = rn * 128 + ((cB ^ (rn & 7)) << 4);
            uint32_t bh4[4], bl4[4];
            ldmx4(bh4, kh + boff);
            ldmx4(bl4, kl + boff);
            mma_bf16(acc[jp * 2], aH, bh4);
            mma_bf16(acc[jp * 2], aH, bl4);
            mma_bf16(acc[jp * 2], aL, bh4);
            mma_bf16(acc[jp * 2 + 1], aH, bh4 + 2);
            mma_bf16(acc[jp * 2 + 1], aH, bl4 + 2);
            mma_bf16(acc[jp * 2 + 1], aL, bh4 + 2);
        }
    }
}

__global__ __launch_bounds__(256, 2)
void attn_mma(float* __restrict__ attnp) {
    extern __shared__ char sax[];
    float* sMp = (float*)(sax + SMP);
    float* sLp = (float*)(sax + SLP);

    const int qt = blockIdx.x, h = blockIdx.y, b = blockIdx.z;
    const int q0 = qt * 64;
    const int tid = threadIdx.x, lane = tid & 31, w = tid >> 5;
    const int wm = (w >> 1) << 4;
    const int wnh = w & 1;
    const int g = lane >> 2, tg = lane & 3;

    const int lo  = max(0, q0 - WIN);
    const int hi  = min(SEQ - 1, q0 + 63 + WIN);
    const int cnt = hi - lo + 1;
    const int nch = (cnt + 127) >> 7;

    const uint32_t qh = s2u(sax) + SQH, ql = s2u(sax) + SQL;
    const uint32_t kh = s2u(sax) + SKH, kl = s2u(sax) + SKL;
    const uint32_t vh = s2u(sax) + SVH, vl = s2u(sax) + SVL;

    const size_t hoff = (size_t)(b * SEQ) * DMODEL + h * DK;
    const __nv_bfloat16* Qh = g_pr_hi + hoff;
    const __nv_bfloat16* Ql = g_pr_lo + hoff;
    const __nv_bfloat16* Kh = g_pr_hi + TSZ + hoff;
    const __nv_bfloat16* Kl = g_pr_lo + TSZ + hoff;
    const __nv_bfloat16* Vh = g_pr_hi + 2 * (size_t)TSZ + hoff;
    const __nv_bfloat16* Vl = g_pr_lo + 2 * (size_t)TSZ + hoff;

    // ---- Q tile via cp.async ----
    #pragma unroll
    for (int it = 0; it < 4; it++) {
        int f = tid + it * 256;
        int buf = f >> 9;
        int rr = (f >> 3) & 63;
        int gr = f & 7;
        const __nv_bfloat16* s = (buf ? Ql : Qh) + (size_t)(q0 + rr) * DMODEL + gr * 8;
        uint32_t d = (buf ? ql : qh) + rr * 128 + ((gr ^ (rr & 7)) << 4);
        CP_ASYNC16(d, s);
    }
    CP_COMMIT();

    const int qg0 = q0 + wm + g, qg1 = qg0 + 8;
    const int jlo0 = max(lo, qg0 - WIN), jhi0 = min(hi, qg0 + WIN);
    const int jlo1 = max(lo, qg1 - WIN), jhi1 = min(hi, qg1 + WIN);

    // ---- pass 1: online (m, l), K double-buffered across (kh,kl)/(vh,vl) ----
    attn_cp128(Kh, Kl, kh, kl, lo, hi, tid);
    CP_COMMIT();

    float m0 = -1e30f, m1 = -1e30f, l0 = 0.f, l1 = 0.f;
    for (int c = 0; c < nch; c++) {
        if (c + 1 < nch) {
            uint32_t dh = ((c + 1) & 1) ? vh : kh;
            uint32_t dl = ((c + 1) & 1) ? vl : kl;
            attn_cp128(Kh, Kl, dh, dl, lo + (c + 1) * 128, hi, tid);
            CP_COMMIT();
            CP_WAIT1();
        } else {
            CP_WAIT0();
        }
        __syncthreads();

        uint32_t ch_ = (c & 1) ? vh : kh;
        uint32_t cl_ = (c & 1) ? vl : kl;
        float acc[8][4];
        qk_mma(acc, qh, ql, ch_, cl_, wm, wnh, lane);

        const int cb = lo + c * 128 + wnh * 64;
        float cmax0 = -1e30f, cmax1 = -1e30f;
        #pragma unroll
        for (int j = 0; j < 8; j++) {
            int jg = cb + j * 8 + tg * 2;
            #pragma unroll
            for (int u = 0; u < 4; u++) acc[j][u] *= 0.125f;
            if (jg     >= jlo0 && jg     <= jhi0) cmax0 = fmaxf(cmax0, acc[j][0]);
            if (jg + 1 >= jlo0 && jg + 1 <= jhi0) cmax0 = fmaxf(cmax0, acc[j][1]);
            if (jg     >= jlo1 && jg     <= jhi1) cmax1 = fmaxf(cmax1, acc[j][2]);
            if (jg + 1 >= jlo1 && jg + 1 <= jhi1) cmax1 = fmaxf(cmax1, acc[j][3]);
        }
        cmax0 = fmaxf(cmax0, __shfl_xor_sync(0xffffffffu, cmax0, 1));
        cmax0 = fmaxf(cmax0, __shfl_xor_sync(0xffffffffu, cmax0, 2));
        cmax1 = fmaxf(cmax1, __shfl_xor_sync(0xffffffffu, cmax1, 1));
        cmax1 = fmaxf(cmax1, __shfl_xor_sync(0xffffffffu, cmax1, 2));

        float mn0 = fmaxf(m0, cmax0), mn1 = fmaxf(m1, cmax1);
        float s0 = 0.f, s1 = 0.f;
        #pragma unroll
        for (int j = 0; j < 8; j++) {
            int jg = cb + j * 8 + tg * 2;
            if (jg     >= jlo0 && jg     <= jhi0) s0 += __expf(acc[j][0] - mn0);
            if (jg + 1 >= jlo0 && jg + 1 <= jhi0) s0 += __expf(acc[j][1] - mn0);
            if (jg     >= jlo1 && jg     <= jhi1) s1 += __expf(acc[j][2] - mn1);
            if (jg + 1 >= jlo1 && jg + 1 <= jhi1) s1 += __expf(acc[j][3] - mn1);
        }
        s0 += __shfl_xor_sync(0xffffffffu, s0, 1);
        s0 += __shfl_xor_sync(0xffffffffu, s0, 2);
        s1 += __shfl_xor_sync(0xffffffffu, s1, 1);
        s1 += __shfl_xor_sync(0xffffffffu, s1, 2);

        l0 = (m0 > -1e29f ? l0 * __expf(m0 - mn0) : 0.f) + s0;
        l1 = (m1 > -1e29f ? l1 * __expf(m1 - mn1) : 0.f) + s1;
        m0 = mn0; m1 = mn1;
        __syncthreads();
    }

    // ---- merge halves; prefetch pass-2 chunk 0 under the merge ----
    if (tg == 0) {
        sMp[wnh * 64 + wm + g]     = m0;  sLp[wnh * 64 + wm + g]     = l0;
        sMp[wnh * 64 + wm + g + 8] = m1;  sLp[wnh * 64 + wm + g + 8] = l1;
    }
    attn_cp128(Kh, Kl, kh, kl, lo, hi, tid);
    attn_cp128(Vh, Vl, vh, vl, lo, hi, tid);
    CP_COMMIT();
    __syncthreads();

    float mf0, mf1, li0, li1;
    {
        int r0 = wm + g, r1 = r0 + 8;
        float ma = sMp[r0], mb2 = sMp[64 + r0];
        float la = sLp[r0], lb2 = sLp[64 + r0];
        mf0 = fmaxf(ma, mb2);
        li0 = 1.f / (la * __expf(ma - mf0) + lb2 * __expf(mb2 - mf0));
        ma = sMp[r1]; mb2 = sMp[64 + r1];
        la = sLp[r1]; lb2 = sLp[64 + r1];
        mf1 = fmaxf(ma, mb2);
        li1 = 1.f / (la * __expf(ma - mf1) + lb2 * __expf(mb2 - mf1));
    }

    float* baseA = nullptr;
    if (attnp) {
        baseA = attnp + ((size_t)((b * NHEADS + h) * SEQ + q0)) * SEQ;
        const int z2 = min((int)SEQ, lo + nch * 128);
        for (int f = tid; f < 64 * 512; f += 256) {
            int m = f >> 9, c4 = (f & 511) << 2;
            if (c4 < lo || c4 >= z2)
                stcs4(baseA + (size_t)m * SEQ + c4, make_float4(0.f, 0.f, 0.f, 0.f));
        }
    }

    // ---- pass 2 ----
    float oacc[4][4];
    #pragma unroll
    for (int j = 0; j < 4; j++)
        #pragma unroll
        for (int u = 0; u < 4; u++) oacc[j][u] = 0.f;

    for (int c = 0; c < nch; c++) {
        CP_WAIT0();
        __syncthreads();
        float acc[8][4];
        qk_mma(acc, qh, ql, kh, kl, wm, wnh, lane);

        const int cb = lo + c * 128 + wnh * 64;
        #pragma unroll
        for (int j = 0; j < 8; j++) {
            int jg = cb + j * 8 + tg * 2;
            float p0 = (jg     >= jlo0 && jg     <= jhi0) ? __expf(acc[j][0] * 0.125f - mf0) * li0 : 0.f;
            float p1 = (jg + 1 >= jlo0 && jg + 1 <= jhi0) ? __expf(acc[j][1] * 0.125f - mf0) * li0 : 0.f;
            float p2 = (jg     >= jlo1 && jg     <= jhi1) ? __expf(acc[j][2] * 0.125f - mf1) * li1 : 0.f;
            float p3 = (jg + 1 >= jlo1 && jg + 1 <= jhi1) ? __expf(acc[j][3] * 0.125f - mf1) * li1 : 0.f;
            acc[j][0] = p0; acc[j][1] = p1; acc[j][2] = p2; acc[j][3] = p3;
            if (baseA && jg < SEQ) {
                stcs2(baseA + (size_t)(wm + g) * SEQ + jg,     make_float2(p0, p1));
                stcs2(baseA + (size_t)(wm + g + 8) * SEQ + jg, make_float2(p2, p3));
            }
        }
        __syncthreads();

        #pragma unroll
        for (int j = 0; j < 8; j++) {
            int col = wnh * 64 + j * 8 + tg * 2;
            int sub = col >> 6, c64 = col & 63;
            int r0 = wm + g, r1 = r0 + 8;
            int o0 = sub * 8192 + r0 * 128 + ((((c64 >> 3)) ^ (r0 & 7)) << 4) + (c64 & 7) * 2;
            int o1 = sub * 8192 + r1 * 128 + ((((c64 >> 3)) ^ (r1 & 7)) << 4) + (c64 & 7) * 2;
            *(uint32_t*)(sax + SKH + o0) = hi_pack(acc[j][0], acc[j][1]);
            *(uint32_t*)(sax + SKL + o0) = lo_pack(acc[j][0], acc[j][1]);
            *(uint32_t*)(sax + SKH + o1) = hi_pack(acc[j][2], acc[j][3]);
            *(uint32_t*)(sax + SKL + o1) = lo_pack(acc[j][2], acc[j][3]);
        }
        __syncthreads();

        #pragma unroll
        for (int ks = 0; ks < 8; ks++) {
            uint32_t aH[4], aL[4];
            int ar = wm + (lane & 15);
            int sub = ks >> 2;
            int cA = (ks & 3) * 2 + (lane >> 4);
            uint32_t aoff = sub * 8192 + ar * 128 + ((cA ^ (ar & 7)) << 4);
            ldmx4(aH, kh + aoff);
            ldmx4(aL, kl + aoff);
            #pragma unroll
            for (int jp = 0; jp < 2; jp++) {
                int rv = ks * 16 + (lane & 15);
                int gd = wnh * 4 + jp * 2 + (lane >> 4);
                uint32_t boff = rv * 128 + ((gd ^ (rv & 7)) << 4);
                uint32_t vh4[4], vl4[4];
                ldmx4t(vh4, vh + boff);
                ldmx4t(vl4, vl + boff);
                mma_bf16(oacc[jp * 2], aH, vh4);
                mma_bf16(oacc[jp * 2], aH, vl4);
                mma_bf16(oacc[jp * 2], aL, vh4);
                mma_bf16(oacc[jp * 2 + 1], aH, vh4 + 2);
                mma_bf16(oacc[jp * 2 + 1], aH, vl4 + 2);
                mma_bf16(oacc[jp * 2 + 1], aL, vh4 + 2);
            }
        }

        if (c + 1 < nch) {
            __syncthreads();
            attn_cp128(Kh, Kl, kh, kl, lo + (c + 1) * 128, hi, tid);
            attn_cp128(Vh, Vl, vh, vl, lo + (c + 1) * 128, hi, tid);
            CP_COMMIT();
        }
    }

    // ---- write ctx (fp32, feeds O-proj) ----
    {
        float* cb2 = g_ctx + ((size_t)(b * SEQ + q0 + wm + g)) * DMODEL + h * DK + wnh * 32;
        #pragma unroll
        for (int j = 0; j < 4; j++) {
            int col = j * 8 + tg * 2;
            *(float2*)(cb2 + col)              = make_float2(oacc[j][0], oacc[j][1]);
            *(float2*)(cb2 + 8 * DMODEL + col) = make_float2(oacc[j][2], oacc[j][3]);
        }
    }
}

// ==================== launch ====================
extern "C" void kernel_launch(void* const* d_in, const int* in_sizes, int n_in,
                              void* d_out, int out_size) {
    const float* q  = (const float*)d_in[0];
    const float* k  = (const float*)d_in[1];
    const float* v  = (const float*)d_in[2];
    const float* Wq = (const float*)d_in[3];
    const float* bq = (const float*)d_in[4];
    const float* Wk = (const float*)d_in[5];
    const float* bk = (const float*)d_in[6];
    const float* Wv = (const float*)d_in[7];
    const float* bv = (const float*)d_in[8];
    const float* Wo = (const float*)d_in[9];
    const float* bo = (const float*)d_in[10];

    __nv_bfloat16 *prh, *prl, *wth, *wtl;
    float* ctx;
    cudaGetSymbolAddress((void**)&prh, g_pr_hi);
    cudaGetSymbolAddress((void**)&prl, g_pr_lo);
    cudaGetSymbolAddress((void**)&ctx, g_ctx);
    cudaGetSymbolAddress((void**)&wth, g_wt_hi);
    cudaGetSymbolAddress((void**)&wtl, g_wt_lo);

    const int GEMM_SMEM = 2 * 32768;
    cudaFuncSetAttribute(gemm_mma_qkv, cudaFuncAttributeMaxDynamicSharedMemorySize, GEMM_SMEM);
    cudaFuncSetAttribute(gemm_mma_one, cudaFuncAttributeMaxDynamicSharedMemorySize, GEMM_SMEM);
    cudaFuncSetAttribute(attn_mma, cudaFuncAttributeMaxDynamicSharedMemorySize, ATTN_SMEM_B);

    WPrep wp;
    wp.w[0] = Wq; wp.w[1] = Wk; wp.w[2] = Wv; wp.w[3] = Wo;
    dim3 pgrid(DMODEL / 32, DMODEL / 32, 4);
    prep_w<<<pgrid, 256>>>(wp, wth, wtl);

    GemmJob job;
    const size_t WSZ = (size_t)DMODEL * DMODEL;
    job.A[0] = q;  job.A[1] = k;  job.A[2] = v;
    for (int z = 0; z < 3; z++) {
        job.Bh[z] = wth + (size_t)z * WSZ;
        job.Bl[z] = wtl + (size_t)z * WSZ;
        job.Ch[z] = prh + (size_t)z * TSZ;
        job.Cl[z] = prl + (size_t)z * TSZ;
    }
    job.bias[0] = bq; job.bias[1] = bk; job.bias[2] = bv;

    dim3 ggrid(DMODEL / 128, NTOK / 128, 3);
    gemm_mma_qkv<<<ggrid, 256, GEMM_SMEM>>>(job);

    const size_t OUTE  = (size_t)NTOK * DMODEL;
    const size_t ATTNE = (size_t)BATCH * NHEADS * SEQ * SEQ;
    float* outp  = (float*)d_out;
    float* attnp = ((size_t)out_size >= OUTE + ATTNE) ? (outp + OUTE) : nullptr;

    dim3 agrid(SEQ / 64, NHEADS, BATCH);
    attn_mma<<<agrid, 256, ATTN_SMEM_B>>>(attnp);

    dim3 ogrid(DMODEL / 128, NTOK / 128);
    gemm_mma_one<<<ogrid, 256, GEMM_SMEM>>>(ctx, wth + 3 * WSZ, wtl + 3 * WSZ, bo, outp);
}